// round 2
// baseline (speedup 1.0000x reference)
#include <cuda_runtime.h>

#define BB 2048
#define SS 512
#define DD 128
#define HH 64
#define OO 8
#define KTOT 192            // D + H
#define BR 16               // batch rows per block
#define NBLK (BB / BR)      // 128 blocks
#define NTHR 128            // 4 warps
#define WRS 192             // w row stride (floats)
#define XRS 196             // xh row stride (floats) -> conflict-free LDS.128
#define SMEM_FLOATS (HH * WRS + BR * XRS)

typedef unsigned long long ull;

__device__ __forceinline__ void fma2(ull& d, ull a, ull b) {
    asm("fma.rn.f32x2 %0, %1, %2, %0;" : "+l"(d) : "l"(a), "l"(b));
}
__device__ __forceinline__ float fsum2(ull v) {
    float lo, hi;
    asm("mov.b64 {%0,%1}, %2;" : "=f"(lo), "=f"(hi) : "l"(v));
    return lo + hi;
}

// ---------------------------------------------------------------------------
// Persistent recurrent kernel: h_{t+1} = relu(x_t @ W_ih^T + bias + h_t @ W_hh^T)
// One block owns BR=16 batch rows for all 512 steps. W (as [j][k], k = 0..191
// spanning W_ih|W_hh) lives in shared for the whole kernel; per-step the
// [x_t | h_t] concatenated operand lives in shared per row. Thread tile:
// 2 rows x 4 j, k packed into f32x2 (even/odd partial sums).
// ---------------------------------------------------------------------------
__global__ __launch_bounds__(NTHR) void rnn_kernel(
    const float* __restrict__ x, const float* __restrict__ h0,
    const float* __restrict__ W_ih, const float* __restrict__ W_hh,
    const float* __restrict__ b_ih, const float* __restrict__ b_hh,
    float* __restrict__ hT)
{
    extern __shared__ float smem[];
    float* wsh = smem;              // [HH][WRS]
    float* xh  = smem + HH * WRS;   // [BR][XRS]: [0,128) = x_t, [128,192) = h_t

    const int tid = threadIdx.x;
    const int rg  = tid & 7;        // row group: rows rg and rg+8
    const int jg  = tid >> 3;       // 0..15
    const int j0  = jg * 4;         // 4 consecutive outputs
    const int brow0 = blockIdx.x * BR;

    // Load weights into shared: wsh[j][0:128) = W_ih[j][:], wsh[j][128:192) = W_hh[j][:]
    for (int i = tid; i < HH * DD; i += NTHR)
        wsh[(i / DD) * WRS + (i % DD)] = W_ih[i];
    for (int i = tid; i < HH * HH; i += NTHR)
        wsh[(i / HH) * WRS + DD + (i % HH)] = W_hh[i];
    // Init h from h0 (shape [1,B,H])
    for (int i = tid; i < BR * HH; i += NTHR)
        xh[(i / HH) * XRS + DD + (i % HH)] = h0[(brow0 + i / HH) * HH + (i % HH)];

    const float bias0 = b_ih[j0 + 0] + b_hh[j0 + 0];
    const float bias1 = b_ih[j0 + 1] + b_hh[j0 + 1];
    const float bias2 = b_ih[j0 + 2] + b_hh[j0 + 2];
    const float bias3 = b_ih[j0 + 3] + b_hh[j0 + 3];

    // x staging: thread stages 16 floats of row (tid>>3), cols [(tid&7)*16, +16)
    const int xrow = tid >> 3;
    const int xcol = (tid & 7) * 16;
    const float* xsrc = x + ((long long)(brow0 + xrow) * SS) * DD + xcol;
    float* xstage = xh + xrow * XRS + xcol;

    // prefetch x_0
    float4 xa0 = *(const float4*)(xsrc + 0);
    float4 xa1 = *(const float4*)(xsrc + 4);
    float4 xa2 = *(const float4*)(xsrc + 8);
    float4 xa3 = *(const float4*)(xsrc + 12);

    const float* xr0 = xh + rg * XRS;
    const float* xr1 = xh + (rg + 8) * XRS;
    const float* wp0 = wsh + (j0 + 0) * WRS;
    const float* wp1 = wsh + (j0 + 1) * WRS;
    const float* wp2 = wsh + (j0 + 2) * WRS;
    const float* wp3 = wsh + (j0 + 3) * WRS;

    for (int t = 0; t < SS; ++t) {
        // stage x_t into shared (h_t already there from previous iteration)
        *(float4*)(xstage + 0)  = xa0;
        *(float4*)(xstage + 4)  = xa1;
        *(float4*)(xstage + 8)  = xa2;
        *(float4*)(xstage + 12) = xa3;
        __syncthreads();

        // prefetch x_{t+1} (overlaps the compute below via scoreboard)
        if (t + 1 < SS) {
            const float* p = xsrc + (long long)(t + 1) * DD;
            xa0 = *(const float4*)(p + 0);
            xa1 = *(const float4*)(p + 4);
            xa2 = *(const float4*)(p + 8);
            xa3 = *(const float4*)(p + 12);
        }

        ull a00 = 0, a01 = 0, a02 = 0, a03 = 0;
        ull a10 = 0, a11 = 0, a12 = 0, a13 = 0;
        #pragma unroll 8
        for (int k = 0; k < KTOT; k += 4) {
            ulonglong2 v0 = *(const ulonglong2*)(xr0 + k);
            ulonglong2 v1 = *(const ulonglong2*)(xr1 + k);
            ulonglong2 w0 = *(const ulonglong2*)(wp0 + k);
            ulonglong2 w1 = *(const ulonglong2*)(wp1 + k);
            ulonglong2 w2 = *(const ulonglong2*)(wp2 + k);
            ulonglong2 w3 = *(const ulonglong2*)(wp3 + k);
            fma2(a00, v0.x, w0.x); fma2(a00, v0.y, w0.y);
            fma2(a01, v0.x, w1.x); fma2(a01, v0.y, w1.y);
            fma2(a02, v0.x, w2.x); fma2(a02, v0.y, w2.y);
            fma2(a03, v0.x, w3.x); fma2(a03, v0.y, w3.y);
            fma2(a10, v1.x, w0.x); fma2(a10, v1.y, w0.y);
            fma2(a11, v1.x, w1.x); fma2(a11, v1.y, w1.y);
            fma2(a12, v1.x, w2.x); fma2(a12, v1.y, w2.y);
            fma2(a13, v1.x, w3.x); fma2(a13, v1.y, w3.y);
        }
        float4 h0v = make_float4(fmaxf(fsum2(a00) + bias0, 0.f),
                                 fmaxf(fsum2(a01) + bias1, 0.f),
                                 fmaxf(fsum2(a02) + bias2, 0.f),
                                 fmaxf(fsum2(a03) + bias3, 0.f));
        float4 h1v = make_float4(fmaxf(fsum2(a10) + bias0, 0.f),
                                 fmaxf(fsum2(a11) + bias1, 0.f),
                                 fmaxf(fsum2(a12) + bias2, 0.f),
                                 fmaxf(fsum2(a13) + bias3, 0.f));
        __syncthreads();
        *(float4*)(xh + rg * XRS + DD + j0)       = h0v;
        *(float4*)(xh + (rg + 8) * XRS + DD + j0) = h1v;
    }
    __syncthreads();
    for (int i = tid; i < BR * HH; i += NTHR)
        hT[(brow0 + i / HH) * HH + (i % HH)] = xh[(i / HH) * XRS + DD + (i % HH)];
}

// ---------------------------------------------------------------------------
// Head: BN1 -> fc1 -> relu -> BN2 -> fc2 (training-mode batch stats over B)
// ---------------------------------------------------------------------------
__device__ float g_z1[BB * 16];
__device__ float g_m1[HH], g_r1[HH];
__device__ float g_m2[16], g_r2[16];

__global__ void stats1_kernel(const float* __restrict__ data) {
    int c = blockIdx.x;  // 0..63
    float s = 0.f, s2 = 0.f;
    for (int r = threadIdx.x; r < BB; r += blockDim.x) {
        float v = data[r * HH + c];
        s += v; s2 += v * v;
    }
    __shared__ float sh[256], sh2[256];
    sh[threadIdx.x] = s; sh2[threadIdx.x] = s2;
    __syncthreads();
    for (int st = 128; st > 0; st >>= 1) {
        if (threadIdx.x < st) {
            sh[threadIdx.x]  += sh[threadIdx.x + st];
            sh2[threadIdx.x] += sh2[threadIdx.x + st];
        }
        __syncthreads();
    }
    if (threadIdx.x == 0) {
        float m = sh[0] / BB;
        float var = sh2[0] / BB - m * m;
        g_m1[c] = m;
        g_r1[c] = rsqrtf(var + 1e-5f);
    }
}

__global__ void fc1_kernel(const float* __restrict__ h,
                           const float* __restrict__ g1, const float* __restrict__ be1,
                           const float* __restrict__ W, const float* __restrict__ wb) {
    __shared__ float sc[HH], sf[HH];
    if (threadIdx.x < HH) {
        float a = g_r1[threadIdx.x] * g1[threadIdx.x];
        sc[threadIdx.x] = a;
        sf[threadIdx.x] = be1[threadIdx.x] - g_m1[threadIdx.x] * a;
    }
    __syncthreads();
    int idx = blockIdx.x * blockDim.x + threadIdx.x;  // over 2048*16
    int b = idx >> 4, c = idx & 15;
    float acc = wb[c];
    #pragma unroll
    for (int k = 0; k < HH; k++)
        acc += (h[b * HH + k] * sc[k] + sf[k]) * W[c * HH + k];
    g_z1[idx] = fmaxf(acc, 0.f);
}

__global__ void stats2_kernel() {
    int c = blockIdx.x;  // 0..15
    float s = 0.f, s2 = 0.f;
    for (int r = threadIdx.x; r < BB; r += blockDim.x) {
        float v = g_z1[r * 16 + c];
        s += v; s2 += v * v;
    }
    __shared__ float sh[256], sh2[256];
    sh[threadIdx.x] = s; sh2[threadIdx.x] = s2;
    __syncthreads();
    for (int st = 128; st > 0; st >>= 1) {
        if (threadIdx.x < st) {
            sh[threadIdx.x]  += sh[threadIdx.x + st];
            sh2[threadIdx.x] += sh2[threadIdx.x + st];
        }
        __syncthreads();
    }
    if (threadIdx.x == 0) {
        float m = sh[0] / BB;
        float var = sh2[0] / BB - m * m;
        g_m2[c] = m;
        g_r2[c] = rsqrtf(var + 1e-5f);
    }
}

__global__ void fc2_kernel(const float* __restrict__ g2, const float* __restrict__ be2,
                           const float* __restrict__ W, const float* __restrict__ wb,
                           float* __restrict__ out) {
    __shared__ float sc[16], sf[16];
    if (threadIdx.x < 16) {
        float a = g_r2[threadIdx.x] * g2[threadIdx.x];
        sc[threadIdx.x] = a;
        sf[threadIdx.x] = be2[threadIdx.x] - g_m2[threadIdx.x] * a;
    }
    __syncthreads();
    int idx = blockIdx.x * blockDim.x + threadIdx.x;  // over 2048*8
    int b = idx >> 3, c = idx & 7;
    float acc = wb[c];
    #pragma unroll
    for (int k = 0; k < 16; k++)
        acc += (g_z1[b * 16 + k] * sc[k] + sf[k]) * W[c * 16 + k];
    out[idx] = acc;
}

// ---------------------------------------------------------------------------
extern "C" void kernel_launch(void* const* d_in, const int* in_sizes, int n_in,
                              void* d_out, int out_size) {
    const float* x    = (const float*)d_in[0];
    const float* h0   = (const float*)d_in[1];
    const float* W_ih = (const float*)d_in[2];
    const float* W_hh = (const float*)d_in[3];
    const float* b_ih = (const float*)d_in[4];
    const float* b_hh = (const float*)d_in[5];
    const float* bn1g = (const float*)d_in[6];
    const float* bn1b = (const float*)d_in[7];
    const float* fc1W = (const float*)d_in[8];
    const float* fc1b = (const float*)d_in[9];
    const float* bn2g = (const float*)d_in[10];
    const float* bn2b = (const float*)d_in[11];
    const float* fc2W = (const float*)d_in[12];
    const float* fc2b = (const float*)d_in[13];

    float* out = (float*)d_out;          // [2048, 8]
    float* hT  = out + BB * OO;          // [1, 2048, 64] hidden-state output

    size_t smem = SMEM_FLOATS * sizeof(float);   // ~61.7 KB > 48 KB -> opt in
    cudaFuncSetAttribute(rnn_kernel, cudaFuncAttributeMaxDynamicSharedMemorySize,
                         (int)smem);

    rnn_kernel<<<NBLK, NTHR, smem>>>(x, h0, W_ih, W_hh, b_ih, b_hh, hT);
    stats1_kernel<<<HH, 256>>>(hT);
    fc1_kernel<<<(BB * 16) / 256, 256>>>(hT, bn1g, bn1b, fc1W, fc1b);
    stats2_kernel<<<16, 256>>>();
    fc2_kernel<<<(BB * 8) / 256, 256>>>(bn2g, bn2b, fc2W, fc2b, out);
}